// round 13
// baseline (speedup 1.0000x reference)
#include <cuda_runtime.h>
#include <cstdint>

// FPSampler: farthest point sampling, B=16, N=131072, npoint=1024.
// 128 CTAs, 544 threads (16 worker warps + 1 comm warp), 1 CTA/SM single wave.
// Each CTA serves TWO batches (A = cta>>4, B = A+8), 16 CTAs per batch group,
// 8192 points per chain per CTA, both slabs resident in 192KB SMEM.
// R13 = R11's exact compute + tagged-slot spec-polling, with the exchange moved
// to a dedicated comm warp whose polls are SPECULATIVE (issued a compute-phase
// before their check, checks gated behind DONE barriers). Workers' inter-phase
// wait is only check+bc+arrive (~150 cyc), not the full exchange.

#define BB 16
#define NN 131072
#define NP 1024
#define GG 16                    // CTAs per batch group
#define PTS (NN / GG)            // 8192 points per chain per CTA
#define NTW 512                  // worker threads (16 warps)
#define NT 544                   // total threads (17 warps)
#define NWW 16                   // worker warps
#define JJ 4                     // float4 chunks per worker thread per chain
#define GRID 128                 // physical CTAs
#define SMEM_BYTES (6 * PTS * sizeof(float))   // 2 chains x 3 planes = 192KB

#define BAR_AD 1                 // workers arrive: chain-A wred ready
#define BAR_BB 2                 // comm arrives:   bcB ready
#define BAR_BD 3                 // workers arrive: chain-B wred ready
#define BAR_AB 4                 // comm arrives:   bcA ready

// Slot: 4 aligned u64 words, EACH self-tagged with seq (=it).
//   w0 = [seq:15 bits 49..63 | val:32 bits 17..48 | idx:17 bits 0..16]
//   wx/wy/wz = (seq << 32) | f32_bits
struct alignas(32) Slot4 {
    unsigned long long w0, wx, wy, wz;
};

__device__ Slot4 g_slot[2][BB][GG];

struct StartArg { int s[BB]; };

__global__ void fps_clear_kernel() {
    unsigned long long* p = (unsigned long long*)g_slot;
    int n = 2 * BB * GG * 4;
    for (int i = threadIdx.x; i < n; i += blockDim.x) p[i] = 0ull;
}

// ---------------- helpers ---------------------------------------------------
__device__ __forceinline__ void bar_sync(int id) {
    asm volatile("bar.sync %0, %1;" :: "r"(id), "r"(NT) : "memory");
}
__device__ __forceinline__ void bar_arrive(int id) {
    asm volatile("bar.arrive %0, %1;" :: "r"(id), "r"(NT) : "memory");
}
__device__ __forceinline__ void membar_cta() {
    asm volatile("membar.cta;" ::: "memory");
}
__device__ __forceinline__ unsigned redux_max_u32(unsigned v) {
    unsigned r;
    asm("redux.sync.max.u32 %0, %1, 0xffffffff;" : "=r"(r) : "r"(v));
    return r;
}
__device__ __forceinline__ unsigned long long f2add(unsigned long long a,
                                                    unsigned long long b) {
    unsigned long long r;
    asm("add.rn.f32x2 %0, %1, %2;" : "=l"(r) : "l"(a), "l"(b));
    return r;
}
__device__ __forceinline__ unsigned long long f2mul(unsigned long long a,
                                                    unsigned long long b) {
    unsigned long long r;
    asm("mul.rn.f32x2 %0, %1, %2;" : "=l"(r) : "l"(a), "l"(b));
    return r;
}
__device__ __forceinline__ unsigned long long pack2(float a, float b) {
    unsigned long long r;
    asm("mov.b64 %0, {%1, %2};" : "=l"(r) : "f"(a), "f"(b));
    return r;
}
__device__ __forceinline__ void unpack2(unsigned long long v, float& a, float& b) {
    asm("mov.b64 {%0, %1}, %2;" : "=f"(a), "=f"(b) : "l"(v));
}
__device__ __forceinline__ void st_cg_u64(void* p, unsigned long long v) {
    asm volatile("st.global.cg.u64 [%0], %1;" :: "l"(p), "l"(v) : "memory");
}
__device__ __forceinline__ unsigned long long ld_cg_u64(const void* p) {
    unsigned long long v;
    asm volatile("ld.global.cg.u64 %0, [%1];" : "=l"(v) : "l"(p) : "memory");
    return v;
}

// Distance update + warp-level argmax for one chain (worker threads).
// Bit-exact reference math: scalar-equivalent rn ops via f32x2,
// (dx*dx + dy*dy) + dz*dz, fminf fold, first-index tie-break via post-hoc scan.
__device__ __forceinline__ void compute_chain(
    const ulonglong2* __restrict__ xs2, const ulonglong2* __restrict__ ys2,
    const ulonglong2* __restrict__ zs2, float (&dist)[JJ][4],
    float cx, float cy, float cz, int t, int base,
    unsigned& maxb_out, unsigned& maxc_out)
{
    const unsigned long long ncx2 = pack2(-cx, -cx);
    const unsigned long long ncy2 = pack2(-cy, -cy);
    const unsigned long long ncz2 = pack2(-cz, -cz);

    float bv0 = -1.0f, bv1 = -1.0f, bv2 = -1.0f, bv3 = -1.0f;
#pragma unroll
    for (int j = 0; j < JJ; j++) {
        const int c0 = j * NTW + t;           // chunk; points 4c0..4c0+3
        ulonglong2 xq = xs2[c0];
        ulonglong2 yq = ys2[c0];
        ulonglong2 zq = zs2[c0];

        unsigned long long dxa = f2add(xq.x, ncx2);
        unsigned long long dxb = f2add(xq.y, ncx2);
        unsigned long long dya = f2add(yq.x, ncy2);
        unsigned long long dyb = f2add(yq.y, ncy2);
        unsigned long long dza = f2add(zq.x, ncz2);
        unsigned long long dzb = f2add(zq.y, ncz2);
        unsigned long long sa =
            f2add(f2add(f2mul(dxa, dxa), f2mul(dya, dya)), f2mul(dza, dza));
        unsigned long long sb =
            f2add(f2add(f2mul(dxb, dxb), f2mul(dyb, dyb)), f2mul(dzb, dzb));

        float d0, d1, d2, d3;
        unpack2(sa, d0, d1);
        unpack2(sb, d2, d3);

        float nd;
        nd = fminf(dist[j][0], d0); dist[j][0] = nd; bv0 = fmaxf(bv0, nd);
        nd = fminf(dist[j][1], d1); dist[j][1] = nd; bv1 = fmaxf(bv1, nd);
        nd = fminf(dist[j][2], d2); dist[j][2] = nd; bv2 = fmaxf(bv2, nd);
        nd = fminf(dist[j][3], d3); dist[j][3] = nd; bv3 = fmaxf(bv3, nd);
    }
    const float bestv = fmaxf(fmaxf(bv0, bv1), fmaxf(bv2, bv3));

    const unsigned mybits = __float_as_uint(bestv);   // d>=0 -> monotone bits
    const unsigned maxb = redux_max_u32(mybits);
    const float maxvf = __uint_as_float(maxb);
    unsigned cand = 0;    // max of ~idx over matches == smallest matching idx
#pragma unroll
    for (int j = 0; j < JJ; j++)
#pragma unroll
        for (int e = 0; e < 4; e++) {
            unsigned ni = 0xFFFFFFFFu - (unsigned)(base + 4 * (j * NTW + t) + e);
            if (dist[j][e] == maxvf) cand = (cand > ni) ? cand : ni;
        }
    maxb_out = maxb;
    maxc_out = redux_max_u32(cand);                   // tie -> smallest idx
}

// Comm-warp CTA reduce over wred + publish this CTA's winner (lane 0).
__device__ __forceinline__ void reduce_publish(
    const unsigned long long* wred, int lane, int it, int buf, int batch,
    int rank, int base, const float* xs, const float* ys, const float* zs)
{
    unsigned long long wv = (lane < NWW) ? wred[lane] : 0ull;
    unsigned hb = (unsigned)(wv >> 32);
    unsigned maxhb = redux_max_u32(hb);
    unsigned lb = (hb == maxhb) ? (unsigned)(wv & 0xFFFFFFFFull) : 0u;
    unsigned maxlb = redux_max_u32(lb);

    if (lane == 0) {
        unsigned gidx = 0xFFFFFFFFu - maxlb;          // batch-global winner idx
        int lp = (int)gidx - base;                    // CTA-local winner
        const unsigned long long seq32 = ((unsigned long long)it << 32);
        Slot4* sl = &g_slot[buf][batch][rank];
        st_cg_u64(&sl->wx, seq32 | __float_as_uint(xs[lp]));
        st_cg_u64(&sl->wy, seq32 | __float_as_uint(ys[lp]));
        st_cg_u64(&sl->wz, seq32 | __float_as_uint(zs[lp]));
        st_cg_u64(&sl->w0, ((unsigned long long)it << 49) |
                           ((unsigned long long)maxhb << 17) |
                           (unsigned long long)(gidx & 0x1FFFFu));
    }
    __syncwarp();
}

// Speculative issue of one lane's slot words (lanes 0..GG-1).
__device__ __forceinline__ void spec_issue(
    int lane, int buf, int batch,
    unsigned long long& w0, unsigned long long& wx,
    unsigned long long& wy, unsigned long long& wz)
{
    if (lane < GG) {
        const Slot4* sl = &g_slot[buf][batch][lane];
        w0 = ld_cg_u64(&sl->w0);
        wx = ld_cg_u64(&sl->wx);
        wy = ld_cg_u64(&sl->wy);
        wz = ld_cg_u64(&sl->wz);
    }
}

// Warp-uniform tagged poll using PRELOADED words first; reload only on miss.
__device__ __forceinline__ void poll_group_spec(
    unsigned long long w0, unsigned long long wx,
    unsigned long long wy, unsigned long long wz,
    int lane, int it, int buf, int batch,
    unsigned& ox, unsigned& oy, unsigned& oz, unsigned& oidx)
{
    const Slot4* sl = &g_slot[buf][batch][lane & (GG - 1)];
    const unsigned u = (unsigned)it;
    bool ok = (lane >= GG) ||
              ((((unsigned)(w0 >> 49) == u) &
                ((unsigned)(wx >> 32) == u) &
                ((unsigned)(wy >> 32) == u) &
                ((unsigned)(wz >> 32) == u)) != 0);
    while (!__all_sync(0xFFFFFFFFu, ok)) {
        if (lane < GG) {
            w0 = ld_cg_u64(&sl->w0);
            wx = ld_cg_u64(&sl->wx);
            wy = ld_cg_u64(&sl->wy);
            wz = ld_cg_u64(&sl->wz);
            ok = (((unsigned)(w0 >> 49) == u) &
                  ((unsigned)(wx >> 32) == u) &
                  ((unsigned)(wy >> 32) == u) &
                  ((unsigned)(wz >> 32) == u)) != 0;
        } else {
            ok = true;
        }
    }

    unsigned val_j = 0u, nidx_j = 0u, xb_j = 0u, yb_j = 0u, zb_j = 0u;
    if (lane < GG) {
        val_j  = (unsigned)((w0 >> 17) & 0xFFFFFFFFull);
        nidx_j = 0xFFFFFFFFu - (unsigned)(w0 & 0x1FFFFull);
        xb_j = (unsigned)wx;
        yb_j = (unsigned)wy;
        zb_j = (unsigned)wz;
    }
    const unsigned maxh = redux_max_u32(val_j);
    const unsigned lj = (val_j == maxh) ? nidx_j : 0u;
    const unsigned maxl = redux_max_u32(lj);          // tie -> smallest idx
    const unsigned m = __ballot_sync(0xFFFFFFFFu,
                        lane < GG && val_j == maxh && nidx_j == maxl);
    const int wl = __ffs((int)m) - 1;
    ox = __shfl_sync(0xFFFFFFFFu, xb_j, wl);
    oy = __shfl_sync(0xFFFFFFFFu, yb_j, wl);
    oz = __shfl_sync(0xFFFFFFFFu, zb_j, wl);
    oidx = 0xFFFFFFFFu - maxl;
}

__global__ void __launch_bounds__(NT, 1)
fps_main_kernel(const float* __restrict__ xyz, float* __restrict__ out, StartArg st)
{
    extern __shared__ float smem[];
    float* xsA = smem;
    float* ysA = smem + PTS;
    float* zsA = smem + 2 * PTS;
    float* xsB = smem + 3 * PTS;
    float* ysB = smem + 4 * PTS;
    float* zsB = smem + 5 * PTS;
    const ulonglong2* xsA2 = (const ulonglong2*)xsA;
    const ulonglong2* ysA2 = (const ulonglong2*)ysA;
    const ulonglong2* zsA2 = (const ulonglong2*)zsA;
    const ulonglong2* xsB2 = (const ulonglong2*)xsB;
    const ulonglong2* ysB2 = (const ulonglong2*)ysB;
    const ulonglong2* zsB2 = (const ulonglong2*)zsB;

    __shared__ unsigned long long wredA[NWW], wredB[NWW];
    __shared__ unsigned bcA[4], bcB[4];   // x,y,z,idx bits

    const int cta  = blockIdx.x;
    const int bA   = cta >> 4;            // batch A: 0..7
    const int bB   = bA + 8;              // batch B: 8..15
    const int rank = cta & (GG - 1);      // rank within group: 0..15
    const int t    = threadIdx.x;
    const int lane = t & 31;
    const int wid  = t >> 5;              // 0..15 workers, 16 comm
    const int base = rank * PTS;          // first batch-global point index

    const float* xbA = xyz + (size_t)bA * NN * 3;
    const float* xbB = xyz + (size_t)bB * NN * 3;
    float* out_xyz = out;
    float* out_idx = out + (size_t)BB * NP * 3;

    // One-time load of both slabs into SMEM planes (all 544 threads).
    for (int p = t; p < PTS; p += NT) {
        const float* sA = xbA + (size_t)(base + p) * 3;
        xsA[p] = sA[0]; ysA[p] = sA[1]; zsA[p] = sA[2];
        const float* sB = xbB + (size_t)(base + p) * 3;
        xsB[p] = sB[0]; ysB[p] = sB[1]; zsB[p] = sB[2];
    }

    // First centroids (broadcast loads).
    const int fiA = st.s[bA];
    const int fiB = st.s[bB];
    const float icxA = xbA[(size_t)fiA * 3 + 0];
    const float icyA = xbA[(size_t)fiA * 3 + 1];
    const float iczA = xbA[(size_t)fiA * 3 + 2];
    const float icxB = xbB[(size_t)fiB * 3 + 0];
    const float icyB = xbB[(size_t)fiB * 3 + 1];
    const float iczB = xbB[(size_t)fiB * 3 + 2];

    if (t == 0) {
        // preset bc (read by workers at it==1 for chain B)
        bcA[0] = __float_as_uint(icxA); bcA[1] = __float_as_uint(icyA);
        bcA[2] = __float_as_uint(iczA); bcA[3] = (unsigned)fiA;
        bcB[0] = __float_as_uint(icxB); bcB[1] = __float_as_uint(icyB);
        bcB[2] = __float_as_uint(iczB); bcB[3] = (unsigned)fiB;
        if (rank == 0) {
            size_t oA = (size_t)bA * NP * 3;
            out_xyz[oA + 0] = icxA; out_xyz[oA + 1] = icyA; out_xyz[oA + 2] = iczA;
            out_idx[(size_t)bA * NP] = (float)fiA;
            size_t oB = (size_t)bB * NP * 3;
            out_xyz[oB + 0] = icxB; out_xyz[oB + 1] = icyB; out_xyz[oB + 2] = iczB;
            out_idx[(size_t)bB * NP] = (float)fiB;
        }
    }
    __syncthreads();

    if (wid < NWW) {
        // ===================== WORKER WARPS =====================
        float distA[JJ][4], distB[JJ][4];
#pragma unroll
        for (int j = 0; j < JJ; j++)
#pragma unroll
            for (int e = 0; e < 4; e++) { distA[j][e] = 1e10f; distB[j][e] = 1e10f; }

        float cxA = icxA, cyA = icyA, czA = iczA;
        float cxB = icxB, cyB = icyB, czB = iczB;

        for (int it = 1; it < NP; it++) {
            // computeA(it) with centroid A(it-1)
            {
                unsigned mb, mc;
                compute_chain(xsA2, ysA2, zsA2, distA, cxA, cyA, czA, t, base, mb, mc);
                if (lane == 0) wredA[wid] = ((unsigned long long)mb << 32) | mc;
            }
            membar_cta();
            bar_arrive(BAR_AD);

            bar_sync(BAR_BB);                 // bcB(it-1) ready
            cxB = __uint_as_float(bcB[0]);
            cyB = __uint_as_float(bcB[1]);
            czB = __uint_as_float(bcB[2]);

            // computeB(it) with centroid B(it-1)
            {
                unsigned mb, mc;
                compute_chain(xsB2, ysB2, zsB2, distB, cxB, cyB, czB, t, base, mb, mc);
                if (lane == 0) wredB[wid] = ((unsigned long long)mb << 32) | mc;
            }
            membar_cta();
            bar_arrive(BAR_BD);

            bar_sync(BAR_AB);                 // bcA(it) ready
            cxA = __uint_as_float(bcA[0]);
            cyA = __uint_as_float(bcA[1]);
            czA = __uint_as_float(bcA[2]);
        }
    } else {
        // ===================== COMM WARP (wid 16) =====================
        unsigned long long sB0 = 0, sBx = 0, sBy = 0, sBz = 0;   // spec regs B
        for (int it = 1; it < NP; it++) {
            const int buf  = it & 1;
            const int bufp = (it - 1) & 1;

            bar_sync(BAR_AD);                 // wredA(it) ready

            // check B(it-1) with spec regs issued at end of previous iter
            if (it >= 2) {
                unsigned ox, oy, oz, oidx;
                poll_group_spec(sB0, sBx, sBy, sBz,
                                lane, it - 1, bufp, bB, ox, oy, oz, oidx);
                if (lane == 0) {
                    bcB[0] = ox; bcB[1] = oy; bcB[2] = oz; bcB[3] = oidx;
                    if (rank == 0) {
                        size_t o3 = ((size_t)bB * NP + (it - 1)) * 3;
                        out_xyz[o3 + 0] = __uint_as_float(ox);
                        out_xyz[o3 + 1] = __uint_as_float(oy);
                        out_xyz[o3 + 2] = __uint_as_float(oz);
                        out_idx[(size_t)bB * NP + (it - 1)] = (float)oidx;
                    }
                }
            }
            membar_cta();
            bar_arrive(BAR_BB);               // release workers into computeB

            // overlapped with workers' computeB:
            reduce_publish(wredA, lane, it, buf, bA, rank, base, xsA, ysA, zsA);
            unsigned long long sA0 = 0, sAx = 0, sAy = 0, sAz = 0;
            spec_issue(lane, buf, bA, sA0, sAx, sAy, sAz);

            bar_sync(BAR_BD);                 // wredB(it) ready

            // check A(it): spec issued ~computeB ago -> near-certain hit
            {
                unsigned ox, oy, oz, oidx;
                poll_group_spec(sA0, sAx, sAy, sAz,
                                lane, it, buf, bA, ox, oy, oz, oidx);
                if (lane == 0) {
                    bcA[0] = ox; bcA[1] = oy; bcA[2] = oz; bcA[3] = oidx;
                    if (rank == 0) {
                        size_t o3 = ((size_t)bA * NP + it) * 3;
                        out_xyz[o3 + 0] = __uint_as_float(ox);
                        out_xyz[o3 + 1] = __uint_as_float(oy);
                        out_xyz[o3 + 2] = __uint_as_float(oz);
                        out_idx[(size_t)bA * NP + it] = (float)oidx;
                    }
                }
            }
            membar_cta();
            bar_arrive(BAR_AB);               // release workers into next iter

            // overlapped with workers' computeA(it+1):
            reduce_publish(wredB, lane, it, buf, bB, rank, base, xsB, ysB, zsB);
            spec_issue(lane, buf, bB, sB0, sBx, sBy, sBz);
        }

        // epilogue: resolve and write chain B's final winner B(NP-1)
        {
            unsigned ox, oy, oz, oidx;
            poll_group_spec(sB0, sBx, sBy, sBz,
                            lane, NP - 1, (NP - 1) & 1, bB, ox, oy, oz, oidx);
            if (lane == 0 && rank == 0) {
                size_t o3 = ((size_t)bB * NP + (NP - 1)) * 3;
                out_xyz[o3 + 0] = __uint_as_float(ox);
                out_xyz[o3 + 1] = __uint_as_float(oy);
                out_xyz[o3 + 2] = __uint_as_float(oz);
                out_idx[(size_t)bB * NP + (NP - 1)] = (float)oidx;
            }
        }
    }
}

// ---------------------------------------------------------------------------
// Host-side reproduction of JAX Threefry RNG for `start` (verified exact R1):
//   start = randint(fold_in(key(0), 1), (16,), 0, 131072), partitionable mode.
// ---------------------------------------------------------------------------
static void tf2x32(uint32_t k0, uint32_t k1, uint32_t c0, uint32_t c1,
                   uint32_t* o0, uint32_t* o1)
{
    uint32_t ks[3] = { k0, k1, k0 ^ k1 ^ 0x1BD11BDAu };
    uint32_t x0 = c0 + ks[0];
    uint32_t x1 = c1 + ks[1];
    static const int rot[2][4] = { {13, 15, 26, 6}, {17, 29, 16, 24} };
    for (int i = 0; i < 5; i++) {
        const int* r = rot[i & 1];
        for (int j = 0; j < 4; j++) {
            x0 += x1;
            x1 = (x1 << r[j]) | (x1 >> (32 - r[j]));
            x1 ^= x0;
        }
        x0 += ks[(i + 1) % 3];
        x1 += ks[(i + 2) % 3] + (uint32_t)(i + 1);
    }
    *o0 = x0;
    *o1 = x1;
}

static void compute_start(int* s)
{
    uint32_t K0, K1;
    tf2x32(0u, 0u, 0u, 1u, &K0, &K1);       // fold_in(key(0), 1)
    uint32_t b0, b1;
    tf2x32(K0, K1, 0u, 1u, &b0, &b1);       // partitionable split, lower key
    for (int i = 0; i < BB; i++) {
        uint32_t y0, y1;
        tf2x32(b0, b1, 0u, (uint32_t)i, &y0, &y1);
        s[i] = (int)((y0 ^ y1) & (uint32_t)(NN - 1));   // span = 2^17
    }
}

extern "C" void kernel_launch(void* const* d_in, const int* in_sizes, int n_in,
                              void* d_out, int out_size)
{
    const float* xyz = (const float*)d_in[0];
    float* out = (float*)d_out;

    StartArg st;
    compute_start(st.s);

    cudaFuncSetAttribute(fps_main_kernel,
                         cudaFuncAttributeMaxDynamicSharedMemorySize,
                         (int)SMEM_BYTES);

    fps_clear_kernel<<<1, 256>>>();
    fps_main_kernel<<<GRID, NT, SMEM_BYTES>>>(xyz, out, st);
}

// round 14
// speedup vs baseline: 1.7344x; 1.7344x over previous
#include <cuda_runtime.h>
#include <cstdint>

// FPSampler: farthest point sampling, B=16, N=131072, npoint=1024.
// 128 CTAs, 512 threads, 1 CTA/SM single wave. Two batches per CTA
// (A = cta>>4, B = A+8), 16 CTAs per batch, 8192 pts per chain per CTA.
// R14 = R11's skeleton (4 __syncthreads/iter, tagged slots, spec polling)
// with warp 0 removed from compute (its chunks spread over warps 1-15) and
// running the spec CHECKS concurrently with the workers' compute phases.
// Serial exchange work between barriers is only reduce+publish (~200 cyc).

#define BB 16
#define NN 131072
#define NP 1024
#define GG 16                    // CTAs per batch group
#define PTS (NN / GG)            // 8192 points per chain per CTA
#define NT 512                   // threads per CTA
#define NWK 15                   // worker warps (1..15)
#define GRID 128
#define SMEM_BYTES (6 * PTS * sizeof(float))   // 2 chains x 3 planes = 192KB

// Slot: 4 aligned u64 words, EACH self-tagged with seq (=it).
//   w0 = [seq:15 bits 49..63 | val:32 bits 17..48 | idx:17 bits 0..16]
//   wx/wy/wz = (seq << 32) | f32_bits
struct alignas(32) Slot4 {
    unsigned long long w0, wx, wy, wz;
};

__device__ Slot4 g_slot[2][BB][GG];

struct StartArg { int s[BB]; };

__global__ void fps_clear_kernel() {
    unsigned long long* p = (unsigned long long*)g_slot;
    int n = 2 * BB * GG * 4;
    for (int i = threadIdx.x; i < n; i += blockDim.x) p[i] = 0ull;
}

// ---------------- helpers ---------------------------------------------------
__device__ __forceinline__ unsigned redux_max_u32(unsigned v) {
    unsigned r;
    asm("redux.sync.max.u32 %0, %1, 0xffffffff;" : "=r"(r) : "r"(v));
    return r;
}
__device__ __forceinline__ unsigned long long f2add(unsigned long long a,
                                                    unsigned long long b) {
    unsigned long long r;
    asm("add.rn.f32x2 %0, %1, %2;" : "=l"(r) : "l"(a), "l"(b));
    return r;
}
__device__ __forceinline__ unsigned long long f2mul(unsigned long long a,
                                                    unsigned long long b) {
    unsigned long long r;
    asm("mul.rn.f32x2 %0, %1, %2;" : "=l"(r) : "l"(a), "l"(b));
    return r;
}
__device__ __forceinline__ unsigned long long pack2(float a, float b) {
    unsigned long long r;
    asm("mov.b64 %0, {%1, %2};" : "=l"(r) : "f"(a), "f"(b));
    return r;
}
__device__ __forceinline__ void unpack2(unsigned long long v, float& a, float& b) {
    asm("mov.b64 {%0, %1}, %2;" : "=f"(a), "=f"(b) : "l"(v));
}
__device__ __forceinline__ void st_cg_u64(void* p, unsigned long long v) {
    asm volatile("st.global.cg.u64 [%0], %1;" :: "l"(p), "l"(v) : "memory");
}
__device__ __forceinline__ unsigned long long ld_cg_u64(const void* p) {
    unsigned long long v;
    asm volatile("ld.global.cg.u64 %0, [%1];" : "=l"(v) : "l"(p) : "memory");
    return v;
}

// ---- worker compute: CN chunks (4 pts each) at cid = cbase + j*stride + toff
// Bit-exact reference math: per-element rn via f32x2, (dx*dx+dy*dy)+dz*dz,
// fminf fold, first-index tie-break via post-hoc scan + redux.
template<int CN>
__device__ __forceinline__ void chain_iter(
    const ulonglong2* __restrict__ xs2, const ulonglong2* __restrict__ ys2,
    const ulonglong2* __restrict__ zs2, float (&dist)[CN][4],
    float cx, float cy, float cz, int cbase, int stride, int toff, int base,
    unsigned& maxb_out, unsigned& maxc_out)
{
    const unsigned long long ncx2 = pack2(-cx, -cx);
    const unsigned long long ncy2 = pack2(-cy, -cy);
    const unsigned long long ncz2 = pack2(-cz, -cz);

    float bv0 = -1.0f, bv1 = -1.0f, bv2 = -1.0f, bv3 = -1.0f;
#pragma unroll
    for (int j = 0; j < CN; j++) {
        const int cid = cbase + j * stride + toff;
        ulonglong2 xq = xs2[cid];
        ulonglong2 yq = ys2[cid];
        ulonglong2 zq = zs2[cid];

        unsigned long long dxa = f2add(xq.x, ncx2);
        unsigned long long dxb = f2add(xq.y, ncx2);
        unsigned long long dya = f2add(yq.x, ncy2);
        unsigned long long dyb = f2add(yq.y, ncy2);
        unsigned long long dza = f2add(zq.x, ncz2);
        unsigned long long dzb = f2add(zq.y, ncz2);
        unsigned long long sa =
            f2add(f2add(f2mul(dxa, dxa), f2mul(dya, dya)), f2mul(dza, dza));
        unsigned long long sb =
            f2add(f2add(f2mul(dxb, dxb), f2mul(dyb, dyb)), f2mul(dzb, dzb));

        float d0, d1, d2, d3;
        unpack2(sa, d0, d1);
        unpack2(sb, d2, d3);

        float nd;
        nd = fminf(dist[j][0], d0); dist[j][0] = nd; bv0 = fmaxf(bv0, nd);
        nd = fminf(dist[j][1], d1); dist[j][1] = nd; bv1 = fmaxf(bv1, nd);
        nd = fminf(dist[j][2], d2); dist[j][2] = nd; bv2 = fmaxf(bv2, nd);
        nd = fminf(dist[j][3], d3); dist[j][3] = nd; bv3 = fmaxf(bv3, nd);
    }
    const float bestv = fmaxf(fmaxf(bv0, bv1), fmaxf(bv2, bv3));

    const unsigned mybits = __float_as_uint(bestv);   // d>=0 -> monotone bits
    const unsigned maxb = redux_max_u32(mybits);
    const float maxvf = __uint_as_float(maxb);
    unsigned cand = 0;    // max of ~idx over matches == smallest matching idx
#pragma unroll
    for (int j = 0; j < CN; j++) {
        const int cid = cbase + j * stride + toff;
#pragma unroll
        for (int e = 0; e < 4; e++) {
            unsigned ni = 0xFFFFFFFFu - (unsigned)(base + 4 * cid + e);
            if (dist[j][e] == maxvf) cand = (cand > ni) ? cand : ni;
        }
    }
    maxb_out = maxb;
    maxc_out = redux_max_u32(cand);                   // tie -> smallest idx
}

// ---- worker main loop (warps 1..15) ----------------------------------------
template<int CN>
__device__ void worker_loop(
    const ulonglong2* xsA2, const ulonglong2* ysA2, const ulonglong2* zsA2,
    const ulonglong2* xsB2, const ulonglong2* ysB2, const ulonglong2* zsB2,
    unsigned long long* wredA, unsigned long long* wredB,
    const unsigned* bcA, const unsigned* bcB,
    int cbase, int stride, int toff, int base, int wid, int lane,
    float cxA, float cyA, float czA)
{
    float distA[CN][4], distB[CN][4];
#pragma unroll
    for (int j = 0; j < CN; j++)
#pragma unroll
        for (int e = 0; e < 4; e++) { distA[j][e] = 1e10f; distB[j][e] = 1e10f; }

    for (int it = 1; it < NP; it++) {
        // computeA(it) with centroid A(it-1)
        unsigned mb, mc;
        chain_iter<CN>(xsA2, ysA2, zsA2, distA, cxA, cyA, czA,
                       cbase, stride, toff, base, mb, mc);
        if (lane == 0) wredA[wid - 1] = ((unsigned long long)mb << 32) | mc;
        __syncthreads();   // s1: wredA ready (warp0 finished checkB before this)
        __syncthreads();   // s2: warp0 published A(it), bcB(it-1) visible

        const float cxB = __uint_as_float(bcB[0]);
        const float cyB = __uint_as_float(bcB[1]);
        const float czB = __uint_as_float(bcB[2]);

        // computeB(it) with centroid B(it-1)
        chain_iter<CN>(xsB2, ysB2, zsB2, distB, cxB, cyB, czB,
                       cbase, stride, toff, base, mb, mc);
        if (lane == 0) wredB[wid - 1] = ((unsigned long long)mb << 32) | mc;
        __syncthreads();   // s3: wredB ready (warp0 finished checkA before this)
        __syncthreads();   // s4: warp0 published B(it), bcA(it) visible

        cxA = __uint_as_float(bcA[0]);
        cyA = __uint_as_float(bcA[1]);
        czA = __uint_as_float(bcA[2]);
    }
}

// ---- warp-0 exchange pieces -------------------------------------------------
__device__ __forceinline__ void reduce_publish(
    const unsigned long long* wred, int lane, int it, int buf, int batch,
    int rank, int base, const float* xs, const float* ys, const float* zs)
{
    unsigned long long wv = (lane < NWK) ? wred[lane] : 0ull;
    unsigned hb = (unsigned)(wv >> 32);
    unsigned maxhb = redux_max_u32(hb);
    unsigned lb = (hb == maxhb) ? (unsigned)(wv & 0xFFFFFFFFull) : 0u;
    unsigned maxlb = redux_max_u32(lb);

    if (lane == 0) {
        unsigned gidx = 0xFFFFFFFFu - maxlb;          // batch-global winner idx
        int lp = (int)gidx - base;                    // CTA-local winner
        const unsigned long long seq32 = ((unsigned long long)it << 32);
        Slot4* sl = &g_slot[buf][batch][rank];
        st_cg_u64(&sl->wx, seq32 | __float_as_uint(xs[lp]));
        st_cg_u64(&sl->wy, seq32 | __float_as_uint(ys[lp]));
        st_cg_u64(&sl->wz, seq32 | __float_as_uint(zs[lp]));
        st_cg_u64(&sl->w0, ((unsigned long long)it << 49) |
                           ((unsigned long long)maxhb << 17) |
                           (unsigned long long)(gidx & 0x1FFFFu));
    }
    __syncwarp();
}

__device__ __forceinline__ void spec_issue(
    int lane, int buf, int batch,
    unsigned long long& w0, unsigned long long& wx,
    unsigned long long& wy, unsigned long long& wz)
{
    if (lane < GG) {
        const Slot4* sl = &g_slot[buf][batch][lane];
        w0 = ld_cg_u64(&sl->w0);
        wx = ld_cg_u64(&sl->wx);
        wy = ld_cg_u64(&sl->wy);
        wz = ld_cg_u64(&sl->wz);
    }
}

// Warp-uniform tagged poll using preloaded words; reload only on miss.
__device__ __forceinline__ void poll_group_spec(
    unsigned long long w0, unsigned long long wx,
    unsigned long long wy, unsigned long long wz,
    int lane, int it, int buf, int batch,
    unsigned& ox, unsigned& oy, unsigned& oz, unsigned& oidx)
{
    const Slot4* sl = &g_slot[buf][batch][lane & (GG - 1)];
    const unsigned u = (unsigned)it;
    bool ok = (lane >= GG) ||
              ((((unsigned)(w0 >> 49) == u) &
                ((unsigned)(wx >> 32) == u) &
                ((unsigned)(wy >> 32) == u) &
                ((unsigned)(wz >> 32) == u)) != 0);
    while (!__all_sync(0xFFFFFFFFu, ok)) {
        if (lane < GG) {
            w0 = ld_cg_u64(&sl->w0);
            wx = ld_cg_u64(&sl->wx);
            wy = ld_cg_u64(&sl->wy);
            wz = ld_cg_u64(&sl->wz);
            ok = (((unsigned)(w0 >> 49) == u) &
                  ((unsigned)(wx >> 32) == u) &
                  ((unsigned)(wy >> 32) == u) &
                  ((unsigned)(wz >> 32) == u)) != 0;
        } else {
            ok = true;
        }
    }

    unsigned val_j = 0u, nidx_j = 0u, xb_j = 0u, yb_j = 0u, zb_j = 0u;
    if (lane < GG) {
        val_j  = (unsigned)((w0 >> 17) & 0xFFFFFFFFull);
        nidx_j = 0xFFFFFFFFu - (unsigned)(w0 & 0x1FFFFull);
        xb_j = (unsigned)wx;
        yb_j = (unsigned)wy;
        zb_j = (unsigned)wz;
    }
    const unsigned maxh = redux_max_u32(val_j);
    const unsigned lj = (val_j == maxh) ? nidx_j : 0u;
    const unsigned maxl = redux_max_u32(lj);          // tie -> smallest idx
    const unsigned m = __ballot_sync(0xFFFFFFFFu,
                        lane < GG && val_j == maxh && nidx_j == maxl);
    const int wl = __ffs((int)m) - 1;
    ox = __shfl_sync(0xFFFFFFFFu, xb_j, wl);
    oy = __shfl_sync(0xFFFFFFFFu, yb_j, wl);
    oz = __shfl_sync(0xFFFFFFFFu, zb_j, wl);
    oidx = 0xFFFFFFFFu - maxl;
}

__global__ void __launch_bounds__(NT, 1)
fps_main_kernel(const float* __restrict__ xyz, float* __restrict__ out, StartArg st)
{
    extern __shared__ float smem[];
    float* xsA = smem;
    float* ysA = smem + PTS;
    float* zsA = smem + 2 * PTS;
    float* xsB = smem + 3 * PTS;
    float* ysB = smem + 4 * PTS;
    float* zsB = smem + 5 * PTS;
    const ulonglong2* xsA2 = (const ulonglong2*)xsA;
    const ulonglong2* ysA2 = (const ulonglong2*)ysA;
    const ulonglong2* zsA2 = (const ulonglong2*)zsA;
    const ulonglong2* xsB2 = (const ulonglong2*)xsB;
    const ulonglong2* ysB2 = (const ulonglong2*)ysB;
    const ulonglong2* zsB2 = (const ulonglong2*)zsB;

    __shared__ unsigned long long wredA[NWK], wredB[NWK];
    __shared__ unsigned bcA[4], bcB[4];   // x,y,z,idx bits

    const int cta  = blockIdx.x;
    const int bA   = cta >> 4;            // batch A: 0..7
    const int bB   = bA + 8;              // batch B: 8..15
    const int rank = cta & (GG - 1);      // rank within group: 0..15
    const int t    = threadIdx.x;
    const int lane = t & 31;
    const int wid  = t >> 5;
    const int base = rank * PTS;

    const float* xbA = xyz + (size_t)bA * NN * 3;
    const float* xbB = xyz + (size_t)bB * NN * 3;
    float* out_xyz = out;
    float* out_idx = out + (size_t)BB * NP * 3;

    // One-time load of both slabs into SMEM planes.
    for (int p = t; p < PTS; p += NT) {
        const float* sA = xbA + (size_t)(base + p) * 3;
        xsA[p] = sA[0]; ysA[p] = sA[1]; zsA[p] = sA[2];
        const float* sB = xbB + (size_t)(base + p) * 3;
        xsB[p] = sB[0]; ysB[p] = sB[1]; zsB[p] = sB[2];
    }

    // First centroids.
    const int fiA = st.s[bA];
    const int fiB = st.s[bB];
    const float icxA = xbA[(size_t)fiA * 3 + 0];
    const float icyA = xbA[(size_t)fiA * 3 + 1];
    const float iczA = xbA[(size_t)fiA * 3 + 2];
    const float icxB = xbB[(size_t)fiB * 3 + 0];
    const float icyB = xbB[(size_t)fiB * 3 + 1];
    const float iczB = xbB[(size_t)fiB * 3 + 2];

    if (t == 0) {
        // preset bcB: read by workers at it==1 (chain B initial centroid)
        bcB[0] = __float_as_uint(icxB); bcB[1] = __float_as_uint(icyB);
        bcB[2] = __float_as_uint(iczB); bcB[3] = (unsigned)fiB;
        if (rank == 0) {
            size_t oA = (size_t)bA * NP * 3;
            out_xyz[oA + 0] = icxA; out_xyz[oA + 1] = icyA; out_xyz[oA + 2] = iczA;
            out_idx[(size_t)bA * NP] = (float)fiA;
            size_t oB = (size_t)bB * NP * 3;
            out_xyz[oB + 0] = icxB; out_xyz[oB + 1] = icyB; out_xyz[oB + 2] = iczB;
            out_idx[(size_t)bB * NP] = (float)fiB;
        }
    }
    __syncthreads();

    if (wid == 0) {
        // ================= WARP 0: exchange only =================
        unsigned long long sB0 = 0, sBx = 0, sBy = 0, sBz = 0;
        for (int it = 1; it < NP; it++) {
            const int buf  = it & 1;
            const int bufp = (it - 1) & 1;

            // check B(it-1) CONCURRENTLY with workers' computeA(it);
            // spec-miss retries are absorbed by the compute window.
            if (it >= 2) {
                unsigned ox, oy, oz, oidx;
                poll_group_spec(sB0, sBx, sBy, sBz,
                                lane, it - 1, bufp, bB, ox, oy, oz, oidx);
                if (lane == 0) {
                    bcB[0] = ox; bcB[1] = oy; bcB[2] = oz; bcB[3] = oidx;
                    if (rank == 0) {
                        size_t o3 = ((size_t)bB * NP + (it - 1)) * 3;
                        out_xyz[o3 + 0] = __uint_as_float(ox);
                        out_xyz[o3 + 1] = __uint_as_float(oy);
                        out_xyz[o3 + 2] = __uint_as_float(oz);
                        out_idx[(size_t)bB * NP + (it - 1)] = (float)oidx;
                    }
                }
            }
            __syncthreads();   // s1: wredA(it) ready
            reduce_publish(wredA, lane, it, buf, bA, rank, base, xsA, ysA, zsA);
            unsigned long long sA0 = 0, sAx = 0, sAy = 0, sAz = 0;
            spec_issue(lane, buf, bA, sA0, sAx, sAy, sAz);
            __syncthreads();   // s2: release workers into computeB

            // check A(it) CONCURRENTLY with workers' computeB(it)
            {
                unsigned ox, oy, oz, oidx;
                poll_group_spec(sA0, sAx, sAy, sAz,
                                lane, it, buf, bA, ox, oy, oz, oidx);
                if (lane == 0) {
                    bcA[0] = ox; bcA[1] = oy; bcA[2] = oz; bcA[3] = oidx;
                    if (rank == 0) {
                        size_t o3 = ((size_t)bA * NP + it) * 3;
                        out_xyz[o3 + 0] = __uint_as_float(ox);
                        out_xyz[o3 + 1] = __uint_as_float(oy);
                        out_xyz[o3 + 2] = __uint_as_float(oz);
                        out_idx[(size_t)bA * NP + it] = (float)oidx;
                    }
                }
            }
            __syncthreads();   // s3: wredB(it) ready
            reduce_publish(wredB, lane, it, buf, bB, rank, base, xsB, ysB, zsB);
            spec_issue(lane, buf, bB, sB0, sBx, sBy, sBz);
            __syncthreads();   // s4: release workers into next iter
        }
        // epilogue: resolve and write chain B's final winner B(NP-1)
        {
            unsigned ox, oy, oz, oidx;
            poll_group_spec(sB0, sBx, sBy, sBz,
                            lane, NP - 1, (NP - 1) & 1, bB, ox, oy, oz, oidx);
            if (lane == 0 && rank == 0) {
                size_t o3 = ((size_t)bB * NP + (NP - 1)) * 3;
                out_xyz[o3 + 0] = __uint_as_float(ox);
                out_xyz[o3 + 1] = __uint_as_float(oy);
                out_xyz[o3 + 2] = __uint_as_float(oz);
                out_idx[(size_t)bB * NP + (NP - 1)] = (float)oidx;
            }
        }
    } else if (wid <= 4) {
        // warps 1-4: threads 32..159, 5 chunks each, cids [0, 640)
        worker_loop<5>(xsA2, ysA2, zsA2, xsB2, ysB2, zsB2,
                       wredA, wredB, bcA, bcB,
                       /*cbase=*/0, /*stride=*/128, /*toff=*/t - 32,
                       base, wid, lane, icxA, icyA, iczA);
    } else {
        // warps 5-15: threads 160..511, 4 chunks each, cids [640, 2048)
        worker_loop<4>(xsA2, ysA2, zsA2, xsB2, ysB2, zsB2,
                       wredA, wredB, bcA, bcB,
                       /*cbase=*/640, /*stride=*/352, /*toff=*/t - 160,
                       base, wid, lane, icxA, icyA, iczA);
    }
}

// ---------------------------------------------------------------------------
// Host-side reproduction of JAX Threefry RNG for `start` (verified exact R1):
//   start = randint(fold_in(key(0), 1), (16,), 0, 131072), partitionable mode.
// ---------------------------------------------------------------------------
static void tf2x32(uint32_t k0, uint32_t k1, uint32_t c0, uint32_t c1,
                   uint32_t* o0, uint32_t* o1)
{
    uint32_t ks[3] = { k0, k1, k0 ^ k1 ^ 0x1BD11BDAu };
    uint32_t x0 = c0 + ks[0];
    uint32_t x1 = c1 + ks[1];
    static const int rot[2][4] = { {13, 15, 26, 6}, {17, 29, 16, 24} };
    for (int i = 0; i < 5; i++) {
        const int* r = rot[i & 1];
        for (int j = 0; j < 4; j++) {
            x0 += x1;
            x1 = (x1 << r[j]) | (x1 >> (32 - r[j]));
            x1 ^= x0;
        }
        x0 += ks[(i + 1) % 3];
        x1 += ks[(i + 2) % 3] + (uint32_t)(i + 1);
    }
    *o0 = x0;
    *o1 = x1;
}

static void compute_start(int* s)
{
    uint32_t K0, K1;
    tf2x32(0u, 0u, 0u, 1u, &K0, &K1);       // fold_in(key(0), 1)
    uint32_t b0, b1;
    tf2x32(K0, K1, 0u, 1u, &b0, &b1);       // partitionable split, lower key
    for (int i = 0; i < BB; i++) {
        uint32_t y0, y1;
        tf2x32(b0, b1, 0u, (uint32_t)i, &y0, &y1);
        s[i] = (int)((y0 ^ y1) & (uint32_t)(NN - 1));   // span = 2^17
    }
}

extern "C" void kernel_launch(void* const* d_in, const int* in_sizes, int n_in,
                              void* d_out, int out_size)
{
    const float* xyz = (const float*)d_in[0];
    float* out = (float*)d_out;

    StartArg st;
    compute_start(st.s);

    cudaFuncSetAttribute(fps_main_kernel,
                         cudaFuncAttributeMaxDynamicSharedMemorySize,
                         (int)SMEM_BYTES);

    fps_clear_kernel<<<1, 256>>>();
    fps_main_kernel<<<GRID, NT, SMEM_BYTES>>>(xyz, out, st);
}

// round 15
// speedup vs baseline: 2.8710x; 1.6553x over previous
#include <cuda_runtime.h>
#include <cstdint>

// FPSampler: farthest point sampling, B=16, N=131072, npoint=1024.
// 128 CTAs, 512 threads, 1 CTA/SM single wave. Each CTA serves TWO batches
// (A = cta>>4, B = A+8), 16 CTAs per batch, 8192 points per chain per CTA.
// R15 = R11 (champion) with ONE change: the speculative tagged-slot poll
// loads are issued MID-compute-phase (between the two 2-chunk halves) rather
// than at phase boundaries, making the speculated slot values ~450 cycles
// fresher and converting most spec-miss retry rounds into hits.

#define BB 16
#define NN 131072
#define NP 1024
#define GG 16                    // CTAs per batch group
#define PTS (NN / GG)            // 8192 points per chain per CTA
#define NT 512                   // threads per CTA
#define NW (NT / 32)             // 16 warps
#define JJ 4                     // float4 chunks per thread (4*4 = 16 points)
#define GRID 128                 // physical CTAs
#define SMEM_BYTES (6 * PTS * sizeof(float))   // 2 chains x 3 planes = 192KB

// Slot: 4 aligned u64 words, EACH self-tagged with seq (=it).
//   w0 = [seq:15 bits 49..63 | val:32 bits 17..48 | idx:17 bits 0..16]
//   wx/wy/wz = (seq << 32) | f32_bits
struct alignas(32) Slot4 {
    unsigned long long w0, wx, wy, wz;
};

__device__ Slot4 g_slot[2][BB][GG];

struct StartArg { int s[BB]; };

__global__ void fps_clear_kernel() {
    unsigned long long* p = (unsigned long long*)g_slot;
    int n = 2 * BB * GG * 4;
    for (int i = threadIdx.x; i < n; i += blockDim.x) p[i] = 0ull;
}

// ---------------- helpers ---------------------------------------------------
__device__ __forceinline__ unsigned redux_max_u32(unsigned v) {
    unsigned r;
    asm("redux.sync.max.u32 %0, %1, 0xffffffff;" : "=r"(r) : "r"(v));
    return r;
}
__device__ __forceinline__ unsigned long long f2add(unsigned long long a,
                                                    unsigned long long b) {
    unsigned long long r;
    asm("add.rn.f32x2 %0, %1, %2;" : "=l"(r) : "l"(a), "l"(b));
    return r;
}
__device__ __forceinline__ unsigned long long f2mul(unsigned long long a,
                                                    unsigned long long b) {
    unsigned long long r;
    asm("mul.rn.f32x2 %0, %1, %2;" : "=l"(r) : "l"(a), "l"(b));
    return r;
}
__device__ __forceinline__ unsigned long long pack2(float a, float b) {
    unsigned long long r;
    asm("mov.b64 %0, {%1, %2};" : "=l"(r) : "f"(a), "f"(b));
    return r;
}
__device__ __forceinline__ void unpack2(unsigned long long v, float& a, float& b) {
    asm("mov.b64 {%0, %1}, %2;" : "=f"(a), "=f"(b) : "l"(v));
}
__device__ __forceinline__ void st_cg_u64(void* p, unsigned long long v) {
    asm volatile("st.global.cg.u64 [%0], %1;" :: "l"(p), "l"(v) : "memory");
}
__device__ __forceinline__ unsigned long long ld_cg_u64(const void* p) {
    unsigned long long v;
    asm volatile("ld.global.cg.u64 %0, [%1];" : "=l"(v) : "l"(p) : "memory");
    return v;
}

// ---- one half of a chain's distance update (chunks [J0, J1)) ---------------
// Bit-exact reference math: per-element rn add/mul via f32x2 (x-c == x+(-c)),
// (dx*dx + dy*dy) + dz*dz, fminf fold. bv folding exact (fmaxf, no NaNs).
template<int J0, int J1>
__device__ __forceinline__ void chain_half(
    const ulonglong2* __restrict__ xs2, const ulonglong2* __restrict__ ys2,
    const ulonglong2* __restrict__ zs2, float (&dist)[JJ][4],
    unsigned long long ncx2, unsigned long long ncy2, unsigned long long ncz2,
    int t, float& bv0, float& bv1, float& bv2, float& bv3)
{
#pragma unroll
    for (int j = J0; j < J1; j++) {
        const int c0 = j * NT + t;            // chunk; points 4c0..4c0+3
        ulonglong2 xq = xs2[c0];
        ulonglong2 yq = ys2[c0];
        ulonglong2 zq = zs2[c0];

        unsigned long long dxa = f2add(xq.x, ncx2);
        unsigned long long dxb = f2add(xq.y, ncx2);
        unsigned long long dya = f2add(yq.x, ncy2);
        unsigned long long dyb = f2add(yq.y, ncy2);
        unsigned long long dza = f2add(zq.x, ncz2);
        unsigned long long dzb = f2add(zq.y, ncz2);
        unsigned long long sa =
            f2add(f2add(f2mul(dxa, dxa), f2mul(dya, dya)), f2mul(dza, dza));
        unsigned long long sb =
            f2add(f2add(f2mul(dxb, dxb), f2mul(dyb, dyb)), f2mul(dzb, dzb));

        float d0, d1, d2, d3;
        unpack2(sa, d0, d1);
        unpack2(sb, d2, d3);

        float nd;
        nd = fminf(dist[j][0], d0); dist[j][0] = nd; bv0 = fmaxf(bv0, nd);
        nd = fminf(dist[j][1], d1); dist[j][1] = nd; bv1 = fmaxf(bv1, nd);
        nd = fminf(dist[j][2], d2); dist[j][2] = nd; bv2 = fmaxf(bv2, nd);
        nd = fminf(dist[j][3], d3); dist[j][3] = nd; bv3 = fmaxf(bv3, nd);
    }
}

// ---- warp-level argmax finish (identical to R11) ---------------------------
__device__ __forceinline__ void argmax_finish(
    const float (&dist)[JJ][4], float bv0, float bv1, float bv2, float bv3,
    int t, int base, unsigned& maxb_out, unsigned& maxc_out)
{
    const float bestv = fmaxf(fmaxf(bv0, bv1), fmaxf(bv2, bv3));
    const unsigned mybits = __float_as_uint(bestv);   // d>=0 -> monotone bits
    const unsigned maxb = redux_max_u32(mybits);
    const float maxvf = __uint_as_float(maxb);
    unsigned cand = 0;    // max of ~idx over matches == smallest matching idx
#pragma unroll
    for (int j = 0; j < JJ; j++)
#pragma unroll
        for (int e = 0; e < 4; e++) {
            unsigned ni = 0xFFFFFFFFu - (unsigned)(base + 4 * (j * NT + t) + e);
            if (dist[j][e] == maxvf) cand = (cand > ni) ? cand : ni;
        }
    maxb_out = maxb;
    maxc_out = redux_max_u32(cand);                   // tie -> smallest idx
}

// Warp-0 CTA reduce over wred + publish this CTA's winner (lane 0).
__device__ __forceinline__ void reduce_publish(
    const unsigned long long* wred, int lane, int it, int buf, int batch,
    int rank, int base, const float* xs, const float* ys, const float* zs)
{
    unsigned long long wv = (lane < NW) ? wred[lane] : 0ull;
    unsigned hb = (unsigned)(wv >> 32);
    unsigned maxhb = redux_max_u32(hb);
    unsigned lb = (hb == maxhb) ? (unsigned)(wv & 0xFFFFFFFFull) : 0u;
    unsigned maxlb = redux_max_u32(lb);

    if (lane == 0) {
        unsigned gidx = 0xFFFFFFFFu - maxlb;          // batch-global winner idx
        int lp = (int)gidx - base;                    // CTA-local winner
        const unsigned long long seq32 = ((unsigned long long)it << 32);
        Slot4* sl = &g_slot[buf][batch][rank];
        st_cg_u64(&sl->wx, seq32 | __float_as_uint(xs[lp]));
        st_cg_u64(&sl->wy, seq32 | __float_as_uint(ys[lp]));
        st_cg_u64(&sl->wz, seq32 | __float_as_uint(zs[lp]));
        st_cg_u64(&sl->w0, ((unsigned long long)it << 49) |
                           ((unsigned long long)maxhb << 17) |
                           (unsigned long long)(gidx & 0x1FFFFu));
    }
    __syncwarp();
}

// Speculative issue of one lane's slot words (lanes 0..GG-1). Fire-and-forget.
__device__ __forceinline__ void spec_issue(
    int lane, int buf, int batch,
    unsigned long long& w0, unsigned long long& wx,
    unsigned long long& wy, unsigned long long& wz)
{
    if (lane < GG) {
        const Slot4* sl = &g_slot[buf][batch][lane];
        w0 = ld_cg_u64(&sl->w0);
        wx = ld_cg_u64(&sl->wx);
        wy = ld_cg_u64(&sl->wy);
        wz = ld_cg_u64(&sl->wz);
    }
}

// Warp-0 uniform tagged poll using PRELOADED words first; reload only on miss.
__device__ __forceinline__ void poll_group_spec(
    unsigned long long w0, unsigned long long wx,
    unsigned long long wy, unsigned long long wz,
    int lane, int it, int buf, int batch,
    unsigned& ox, unsigned& oy, unsigned& oz, unsigned& oidx)
{
    const Slot4* sl = &g_slot[buf][batch][lane & (GG - 1)];
    const unsigned u = (unsigned)it;
    bool ok = (lane >= GG) ||
              ((((unsigned)(w0 >> 49) == u) &
                ((unsigned)(wx >> 32) == u) &
                ((unsigned)(wy >> 32) == u) &
                ((unsigned)(wz >> 32) == u)) != 0);
    while (!__all_sync(0xFFFFFFFFu, ok)) {
        if (lane < GG) {
            w0 = ld_cg_u64(&sl->w0);
            wx = ld_cg_u64(&sl->wx);
            wy = ld_cg_u64(&sl->wy);
            wz = ld_cg_u64(&sl->wz);
            ok = (((unsigned)(w0 >> 49) == u) &
                  ((unsigned)(wx >> 32) == u) &
                  ((unsigned)(wy >> 32) == u) &
                  ((unsigned)(wz >> 32) == u)) != 0;
        } else {
            ok = true;
        }
    }

    unsigned val_j = 0u, nidx_j = 0u, xb_j = 0u, yb_j = 0u, zb_j = 0u;
    if (lane < GG) {
        val_j  = (unsigned)((w0 >> 17) & 0xFFFFFFFFull);
        nidx_j = 0xFFFFFFFFu - (unsigned)(w0 & 0x1FFFFull);
        xb_j = (unsigned)wx;
        yb_j = (unsigned)wy;
        zb_j = (unsigned)wz;
    }
    const unsigned maxh = redux_max_u32(val_j);
    const unsigned lj = (val_j == maxh) ? nidx_j : 0u;
    const unsigned maxl = redux_max_u32(lj);          // tie -> smallest idx
    const unsigned m = __ballot_sync(0xFFFFFFFFu,
                        lane < GG && val_j == maxh && nidx_j == maxl);
    const int wl = __ffs((int)m) - 1;
    ox = __shfl_sync(0xFFFFFFFFu, xb_j, wl);
    oy = __shfl_sync(0xFFFFFFFFu, yb_j, wl);
    oz = __shfl_sync(0xFFFFFFFFu, zb_j, wl);
    oidx = 0xFFFFFFFFu - maxl;
}

__global__ void __launch_bounds__(NT, 1)
fps_main_kernel(const float* __restrict__ xyz, float* __restrict__ out, StartArg st)
{
    extern __shared__ float smem[];
    float* xsA = smem;
    float* ysA = smem + PTS;
    float* zsA = smem + 2 * PTS;
    float* xsB = smem + 3 * PTS;
    float* ysB = smem + 4 * PTS;
    float* zsB = smem + 5 * PTS;
    const ulonglong2* xsA2 = (const ulonglong2*)xsA;
    const ulonglong2* ysA2 = (const ulonglong2*)ysA;
    const ulonglong2* zsA2 = (const ulonglong2*)zsA;
    const ulonglong2* xsB2 = (const ulonglong2*)xsB;
    const ulonglong2* ysB2 = (const ulonglong2*)ysB;
    const ulonglong2* zsB2 = (const ulonglong2*)zsB;

    __shared__ unsigned long long wred[NW];
    __shared__ unsigned bcA[4], bcB[4];   // x,y,z,idx bits

    const int cta  = blockIdx.x;
    const int bA   = cta >> 4;            // batch A: 0..7
    const int bB   = bA + 8;              // batch B: 8..15
    const int rank = cta & (GG - 1);      // rank within group: 0..15
    const int t    = threadIdx.x;
    const int lane = t & 31;
    const int warp = t >> 5;
    const int base = rank * PTS;          // first batch-global point index

    const float* xbA = xyz + (size_t)bA * NN * 3;
    const float* xbB = xyz + (size_t)bB * NN * 3;
    float* out_xyz = out;
    float* out_idx = out + (size_t)BB * NP * 3;

    // One-time load of both slabs into SMEM planes.
    for (int p = t; p < PTS; p += NT) {
        const float* sA = xbA + (size_t)(base + p) * 3;
        xsA[p] = sA[0]; ysA[p] = sA[1]; zsA[p] = sA[2];
        const float* sB = xbB + (size_t)(base + p) * 3;
        xsB[p] = sB[0]; ysB[p] = sB[1]; zsB[p] = sB[2];
    }

    float distA[JJ][4], distB[JJ][4];
#pragma unroll
    for (int j = 0; j < JJ; j++)
#pragma unroll
        for (int e = 0; e < 4; e++) { distA[j][e] = 1e10f; distB[j][e] = 1e10f; }

    // First centroids.
    const int fiA = st.s[bA];
    const int fiB = st.s[bB];
    float cxA = xbA[(size_t)fiA * 3 + 0];
    float cyA = xbA[(size_t)fiA * 3 + 1];
    float czA = xbA[(size_t)fiA * 3 + 2];
    float cxB = xbB[(size_t)fiB * 3 + 0];
    float cyB = xbB[(size_t)fiB * 3 + 1];
    float czB = xbB[(size_t)fiB * 3 + 2];

    if (rank == 0 && t == 0) {
        size_t oA = (size_t)bA * NP * 3;
        out_xyz[oA + 0] = cxA; out_xyz[oA + 1] = cyA; out_xyz[oA + 2] = czA;
        out_idx[(size_t)bA * NP] = (float)fiA;
        size_t oB = (size_t)bB * NP * 3;
        out_xyz[oB + 0] = cxB; out_xyz[oB + 1] = cyB; out_xyz[oB + 2] = czB;
        out_idx[(size_t)bB * NP] = (float)fiB;
    }
    __syncthreads();

    for (int it = 1; it < NP; it++) {
        const int buf  = it & 1;
        const int bufp = (it - 1) & 1;

        unsigned long long sB0 = 0, sBx = 0, sBy = 0, sBz = 0;

        // ---- phase 1: compute chain A; spec-issue B(it-1) MID-phase ----
        {
            const unsigned long long ncx2 = pack2(-cxA, -cxA);
            const unsigned long long ncy2 = pack2(-cyA, -cyA);
            const unsigned long long ncz2 = pack2(-czA, -czA);
            float bv0 = -1.0f, bv1 = -1.0f, bv2 = -1.0f, bv3 = -1.0f;
            chain_half<0, 2>(xsA2, ysA2, zsA2, distA, ncx2, ncy2, ncz2,
                             t, bv0, bv1, bv2, bv3);
            if (warp == 0 && it >= 2)
                spec_issue(lane, bufp, bB, sB0, sBx, sBy, sBz);
            chain_half<2, JJ>(xsA2, ysA2, zsA2, distA, ncx2, ncy2, ncz2,
                              t, bv0, bv1, bv2, bv3);
            unsigned mb, mc;
            argmax_finish(distA, bv0, bv1, bv2, bv3, t, base, mb, mc);
            if (lane == 0) wred[warp] = ((unsigned long long)mb << 32) | mc;
        }
        __syncthreads();

        // ---- phase 2: warp0 reduce+publish A(it); check B(it-1) [spec] ----
        if (warp == 0) {
            reduce_publish(wred, lane, it, buf, bA, rank, base, xsA, ysA, zsA);
            if (it >= 2) {
                unsigned ox, oy, oz, oidx;
                poll_group_spec(sB0, sBx, sBy, sBz,
                                lane, it - 1, bufp, bB, ox, oy, oz, oidx);
                if (lane == 0) {
                    bcB[0] = ox; bcB[1] = oy; bcB[2] = oz; bcB[3] = oidx;
                    if (rank == 0) {
                        size_t o3 = ((size_t)bB * NP + (it - 1)) * 3;
                        out_xyz[o3 + 0] = __uint_as_float(ox);
                        out_xyz[o3 + 1] = __uint_as_float(oy);
                        out_xyz[o3 + 2] = __uint_as_float(oz);
                        out_idx[(size_t)bB * NP + (it - 1)] = (float)oidx;
                    }
                }
            }
        }
        __syncthreads();
        if (it >= 2) {
            cxB = __uint_as_float(bcB[0]);
            cyB = __uint_as_float(bcB[1]);
            czB = __uint_as_float(bcB[2]);
        }

        unsigned long long sA0 = 0, sAx = 0, sAy = 0, sAz = 0;

        // ---- phase 3: compute chain B; spec-issue A(it) MID-phase ----
        {
            const unsigned long long ncx2 = pack2(-cxB, -cxB);
            const unsigned long long ncy2 = pack2(-cyB, -cyB);
            const unsigned long long ncz2 = pack2(-czB, -czB);
            float bv0 = -1.0f, bv1 = -1.0f, bv2 = -1.0f, bv3 = -1.0f;
            chain_half<0, 2>(xsB2, ysB2, zsB2, distB, ncx2, ncy2, ncz2,
                             t, bv0, bv1, bv2, bv3);
            if (warp == 0)
                spec_issue(lane, buf, bA, sA0, sAx, sAy, sAz);
            chain_half<2, JJ>(xsB2, ysB2, zsB2, distB, ncx2, ncy2, ncz2,
                              t, bv0, bv1, bv2, bv3);
            unsigned mb, mc;
            argmax_finish(distB, bv0, bv1, bv2, bv3, t, base, mb, mc);
            if (lane == 0) wred[warp] = ((unsigned long long)mb << 32) | mc;
        }
        __syncthreads();

        // ---- phase 4: warp0 reduce+publish B(it); check A(it) [spec] ----
        if (warp == 0) {
            reduce_publish(wred, lane, it, buf, bB, rank, base, xsB, ysB, zsB);
            {
                unsigned ox, oy, oz, oidx;
                poll_group_spec(sA0, sAx, sAy, sAz,
                                lane, it, buf, bA, ox, oy, oz, oidx);
                if (lane == 0) {
                    bcA[0] = ox; bcA[1] = oy; bcA[2] = oz; bcA[3] = oidx;
                    if (rank == 0) {
                        size_t o3 = ((size_t)bA * NP + it) * 3;
                        out_xyz[o3 + 0] = __uint_as_float(ox);
                        out_xyz[o3 + 1] = __uint_as_float(oy);
                        out_xyz[o3 + 2] = __uint_as_float(oz);
                        out_idx[(size_t)bA * NP + it] = (float)oidx;
                    }
                }
            }
        }
        __syncthreads();
        cxA = __uint_as_float(bcA[0]);
        cyA = __uint_as_float(bcA[1]);
        czA = __uint_as_float(bcA[2]);
    }

    // ---- epilogue: retrieve and write chain B's final winner B(NP-1) ----
    if (warp == 0) {
        unsigned ox, oy, oz, oidx;
        poll_group_spec(0, 0, 0, 0,                   // no spec: forces reload
                        lane, NP - 1, (NP - 1) & 1, bB, ox, oy, oz, oidx);
        if (lane == 0 && rank == 0) {
            size_t o3 = ((size_t)bB * NP + (NP - 1)) * 3;
            out_xyz[o3 + 0] = __uint_as_float(ox);
            out_xyz[o3 + 1] = __uint_as_float(oy);
            out_xyz[o3 + 2] = __uint_as_float(oz);
            out_idx[(size_t)bB * NP + (NP - 1)] = (float)oidx;
        }
    }
}

// ---------------------------------------------------------------------------
// Host-side reproduction of JAX Threefry RNG for `start` (verified exact R1):
//   start = randint(fold_in(key(0), 1), (16,), 0, 131072), partitionable mode.
// ---------------------------------------------------------------------------
static void tf2x32(uint32_t k0, uint32_t k1, uint32_t c0, uint32_t c1,
                   uint32_t* o0, uint32_t* o1)
{
    uint32_t ks[3] = { k0, k1, k0 ^ k1 ^ 0x1BD11BDAu };
    uint32_t x0 = c0 + ks[0];
    uint32_t x1 = c1 + ks[1];
    static const int rot[2][4] = { {13, 15, 26, 6}, {17, 29, 16, 24} };
    for (int i = 0; i < 5; i++) {
        const int* r = rot[i & 1];
        for (int j = 0; j < 4; j++) {
            x0 += x1;
            x1 = (x1 << r[j]) | (x1 >> (32 - r[j]));
            x1 ^= x0;
        }
        x0 += ks[(i + 1) % 3];
        x1 += ks[(i + 2) % 3] + (uint32_t)(i + 1);
    }
    *o0 = x0;
    *o1 = x1;
}

static void compute_start(int* s)
{
    uint32_t K0, K1;
    tf2x32(0u, 0u, 0u, 1u, &K0, &K1);       // fold_in(key(0), 1)
    uint32_t b0, b1;
    tf2x32(K0, K1, 0u, 1u, &b0, &b1);       // partitionable split, lower key
    for (int i = 0; i < BB; i++) {
        uint32_t y0, y1;
        tf2x32(b0, b1, 0u, (uint32_t)i, &y0, &y1);
        s[i] = (int)((y0 ^ y1) & (uint32_t)(NN - 1));   // span = 2^17
    }
}

extern "C" void kernel_launch(void* const* d_in, const int* in_sizes, int n_in,
                              void* d_out, int out_size)
{
    const float* xyz = (const float*)d_in[0];
    float* out = (float*)d_out;

    StartArg st;
    compute_start(st.s);

    cudaFuncSetAttribute(fps_main_kernel,
                         cudaFuncAttributeMaxDynamicSharedMemorySize,
                         (int)SMEM_BYTES);

    fps_clear_kernel<<<1, 256>>>();
    fps_main_kernel<<<GRID, NT, SMEM_BYTES>>>(xyz, out, st);
}